// round 1
// baseline (speedup 1.0000x reference)
#include <cuda_runtime.h>

#define FULLMASK 0xffffffffu

// Problem dims (fixed by the dataset)
#define Bb 16
#define Ss 256
#define Nn 16
#define Dd 6
#define Hh 16
#define CHAINS (Bb * Nn)   // 256
#define HW (Hh * 32)       // 512

// Scratch for all rotor states: [chain][t][h][32] = 256*256*16*32 floats = 128 MB
__device__ float g_psi[(size_t)CHAINS * Ss * HW];

// sign of blade product e_a * e_b in Cl(5,0) (Euclidean metric), matches reference
__device__ __forceinline__ int clifford_sign_neg(unsigned a, unsigned b) {
    a >>= 1;
    unsigned s = 0;
    while (a) { s += __popc(a & b); a >>= 1; }
    return (int)(s & 1u);
}

// rsqrt(sum_over_warp(v*v) + 1e-8), identical value on all lanes
__device__ __forceinline__ float warp_rnorm(float v) {
    float s = v * v;
    s += __shfl_xor_sync(FULLMASK, s, 16);
    s += __shfl_xor_sync(FULLMASK, s, 8);
    s += __shfl_xor_sync(FULLMASK, s, 4);
    s += __shfl_xor_sync(FULLMASK, s, 2);
    s += __shfl_xor_sync(FULLMASK, s, 1);
    s += 1e-8f;
    float r = rsqrtf(s);
    // one Newton-Raphson step: keeps 256-step error accumulation well under 1e-3
    r = r * (1.5f - 0.5f * s * r * r);
    return r;
}

// ---------------------------------------------------------------------------
// Phase 1: the sequential rotor recurrence.
// One warp per (chain, head). Lane = blade index. No block-level sync needed.
// Writes normalized psi_t for every step into g_psi.
// ---------------------------------------------------------------------------
__global__ void __launch_bounds__(128) rotor_rnn_kernel(
    const float* __restrict__ x,      // [B,S,N,D]
    const float* __restrict__ W_in,   // [D, H*32]
    const float* __restrict__ b_in)   // [H*32]
{
    const int gw   = (blockIdx.x * blockDim.x + threadIdx.x) >> 5;  // 0..4095
    const int lane = threadIdx.x & 31;
    const int h = gw & (Hh - 1);
    const int c = gw >> 4;            // chain 0..255
    const int b = c >> 4;
    const int n = c & (Nn - 1);
    const int col = h * 32 + lane;

    // W_in column for this lane's blade (reused 256 times -> registers)
    float w[Dd];
#pragma unroll
    for (int d = 0; d < Dd; ++d) w[d] = __ldg(W_in + d * HW + col);
    const float bi = __ldg(b_in + col);

    // Per-lane sign masks: bit pattern 0x80000000 if sgn(i, i^lane) < 0
    unsigned smask[32];
#pragma unroll
    for (int i = 0; i < 32; ++i)
        smask[i] = clifford_sign_neg((unsigned)i, (unsigned)(i ^ lane)) ? 0x80000000u : 0u;

    // psi0 = identity rotor
    float ps = (lane == 0) ? 1.0f : 0.0f;

    const float* xp = x + ((size_t)(b * Ss) * Nn + n) * Dd;  // step stride = Nn*Dd
    float* pp = g_psi + ((size_t)c * Ss) * HW + h * 32 + lane;

    // software-pipelined x loads (warp-uniform broadcast)
    float cx[Dd];
#pragma unroll
    for (int d = 0; d < Dd; ++d) cx[d] = __ldg(xp + d);

    for (int t = 0; t < Ss; ++t) {
        // prefetch next step's x
        const float* xn = xp + Nn * Dd;
        const bool more = (t + 1 < Ss);
        float nx[Dd];
#pragma unroll
        for (int d = 0; d < Dd; ++d) nx[d] = more ? __ldg(xn + d) : 0.0f;

        // u = x_t @ W_in + b_in ; blade0 += 1
        float u = bi;
#pragma unroll
        for (int d = 0; d < Dd; ++d) u = fmaf(w[d], cx[d], u);
        if (lane == 0) u += 1.0f;

        // delta_r = normalize(u)
        float r  = warp_rnorm(u);
        float dl = u * r;

        // geometric product: pn[lane] = sum_i sgn(i, i^lane) * dl[i] * ps[i^lane]
        float pn = 0.0f;
#pragma unroll
        for (int i = 0; i < 32; ++i) {
            float di = __shfl_sync(FULLMASK, dl, i);        // broadcast a[i]
            float pj = __shfl_xor_sync(FULLMASK, ps, i);    // ps[lane^i]
            pn = fmaf(di, __uint_as_float(__float_as_uint(pj) ^ smask[i]), pn);
        }

        // psi = normalize(pn)
        r  = warp_rnorm(pn);
        ps = pn * r;

        *pp = ps;        // coalesced 128B store per warp
        pp += HW;
        xp = xn;
#pragma unroll
        for (int d = 0; d < Dd; ++d) cx[d] = nx[d];
    }
}

// ---------------------------------------------------------------------------
// Phase 2: y[b,t,n,:] = x[b,t,n,:] + psi[b,n,t,:] @ W_out + b_out
// One warp per (chain,t) row; 512-length dot products vs 6 output dims.
// W_out staged in shared, transposed [d][c] for conflict-free LDS.
// ---------------------------------------------------------------------------
__global__ void __launch_bounds__(256) proj_kernel(
    const float* __restrict__ x,      // [B,S,N,D]
    const float* __restrict__ W_out,  // [H*32, D]
    const float* __restrict__ b_out,  // [D]
    float* __restrict__ y)            // [B,S,N,D]
{
    __shared__ float sW[Dd][HW];
    __shared__ float sB[Dd];
    for (int i = threadIdx.x; i < HW * Dd; i += blockDim.x) {
        int cc = i / Dd, d = i % Dd;
        sW[d][cc] = W_out[i];
    }
    if (threadIdx.x < Dd) sB[threadIdx.x] = b_out[threadIdx.x];
    __syncthreads();

    const int warpGlobal = (blockIdx.x * blockDim.x + threadIdx.x) >> 5;  // 0..2047
    const int lane = threadIdx.x & 31;

    for (int rr = 0; rr < 32; ++rr) {
        const int row = warpGlobal + 2048 * rr;            // 0..65535 = chain*256 + t
        const float* pr = g_psi + (size_t)row * HW;

        float a0 = 0.f, a1 = 0.f, a2 = 0.f, a3 = 0.f, a4 = 0.f, a5 = 0.f;
#pragma unroll
        for (int k = 0; k < 16; ++k) {
            const int cc = lane + 32 * k;                  // conflict-free banks
            const float p = __ldg(pr + cc);                // coalesced
            a0 = fmaf(p, sW[0][cc], a0);
            a1 = fmaf(p, sW[1][cc], a1);
            a2 = fmaf(p, sW[2][cc], a2);
            a3 = fmaf(p, sW[3][cc], a3);
            a4 = fmaf(p, sW[4][cc], a4);
            a5 = fmaf(p, sW[5][cc], a5);
        }
#pragma unroll
        for (int o = 16; o; o >>= 1) {
            a0 += __shfl_xor_sync(FULLMASK, a0, o);
            a1 += __shfl_xor_sync(FULLMASK, a1, o);
            a2 += __shfl_xor_sync(FULLMASK, a2, o);
            a3 += __shfl_xor_sync(FULLMASK, a3, o);
            a4 += __shfl_xor_sync(FULLMASK, a4, o);
            a5 += __shfl_xor_sync(FULLMASK, a5, o);
        }

        const int c = row >> 8;
        const int t = row & (Ss - 1);
        const int b = c >> 4;
        const int n = c & (Nn - 1);
        const size_t off = (((size_t)b * Ss + t) * Nn + n) * Dd;
        if (lane < Dd) {
            float av = (lane == 0) ? a0 : (lane == 1) ? a1 : (lane == 2) ? a2
                     : (lane == 3) ? a3 : (lane == 4) ? a4 : a5;
            y[off + lane] = x[off + lane] + av + sB[lane];
        }
    }
}

extern "C" void kernel_launch(void* const* d_in, const int* in_sizes, int n_in,
                              void* d_out, int out_size) {
    const float* x     = (const float*)d_in[0];
    const float* W_in  = (const float*)d_in[1];
    const float* b_in  = (const float*)d_in[2];
    const float* W_out = (const float*)d_in[3];
    const float* b_out = (const float*)d_in[4];
    float* y = (float*)d_out;

    // Phase 1: 4096 warps (256 chains x 16 heads), one warp per recurrence
    rotor_rnn_kernel<<<1024, 128>>>(x, W_in, b_in);
    // Phase 2: 2048 warps x 32 rows each = 65536 output rows
    proj_kernel<<<256, 256>>>(x, W_out, b_out, y);
}

// round 2
// speedup vs baseline: 1.0035x; 1.0035x over previous
#include <cuda_runtime.h>

#define FULLMASK 0xffffffffu

// Problem dims (fixed by the dataset)
#define Bb 16
#define Ss 256
#define Nn 16
#define Dd 6
#define Hh 16
#define CHAINS (Bb * Nn)   // 256
#define HW (Hh * 32)       // 512

// Scratch for all rotor states: [chain][t][h][32] = 256*256*16*32 floats = 128 MB
__device__ float g_psi[(size_t)CHAINS * Ss * HW];

// sign of blade product e_a * e_b in Cl(5,0) (Euclidean metric), matches reference
__device__ __forceinline__ int clifford_sign_neg(unsigned a, unsigned b) {
    a >>= 1;
    unsigned s = 0;
    while (a) { s += __popc(a & b); a >>= 1; }
    return (int)(s & 1u);
}

// rsqrt(sum_over_warp(v*v) + 1e-8), identical value on all lanes
__device__ __forceinline__ float warp_rnorm(float v) {
    float s = v * v;
    s += __shfl_xor_sync(FULLMASK, s, 16);
    s += __shfl_xor_sync(FULLMASK, s, 8);
    s += __shfl_xor_sync(FULLMASK, s, 4);
    s += __shfl_xor_sync(FULLMASK, s, 2);
    s += __shfl_xor_sync(FULLMASK, s, 1);
    s += 1e-8f;
    float r = rsqrtf(s);
    // one Newton-Raphson step: keeps 256-step error accumulation well under 1e-3
    r = r * (1.5f - 0.5f * s * r * r);
    return r;
}

// ---------------------------------------------------------------------------
// Phase 1: the sequential rotor recurrence.
// One warp per (chain, head). Lane = blade index. No block-level sync needed.
// Writes normalized psi_t for every step into g_psi.
// ---------------------------------------------------------------------------
__global__ void __launch_bounds__(128) rotor_rnn_kernel(
    const float* __restrict__ x,      // [B,S,N,D]
    const float* __restrict__ W_in,   // [D, H*32]
    const float* __restrict__ b_in)   // [H*32]
{
    const int gw   = (blockIdx.x * blockDim.x + threadIdx.x) >> 5;  // 0..4095
    const int lane = threadIdx.x & 31;
    const int h = gw & (Hh - 1);
    const int c = gw >> 4;            // chain 0..255
    const int b = c >> 4;
    const int n = c & (Nn - 1);
    const int col = h * 32 + lane;

    // W_in column for this lane's blade (reused 256 times -> registers)
    float w[Dd];
#pragma unroll
    for (int d = 0; d < Dd; ++d) w[d] = __ldg(W_in + d * HW + col);
    const float bi = __ldg(b_in + col);

    // Per-lane sign masks: bit pattern 0x80000000 if sgn(i, i^lane) < 0
    unsigned smask[32];
#pragma unroll
    for (int i = 0; i < 32; ++i)
        smask[i] = clifford_sign_neg((unsigned)i, (unsigned)(i ^ lane)) ? 0x80000000u : 0u;

    // psi0 = identity rotor
    float ps = (lane == 0) ? 1.0f : 0.0f;

    const float* xp = x + ((size_t)(b * Ss) * Nn + n) * Dd;  // step stride = Nn*Dd
    float* pp = g_psi + ((size_t)c * Ss) * HW + h * 32 + lane;

    // software-pipelined x loads (warp-uniform broadcast)
    float cx[Dd];
#pragma unroll
    for (int d = 0; d < Dd; ++d) cx[d] = __ldg(xp + d);

    for (int t = 0; t < Ss; ++t) {
        // prefetch next step's x
        const float* xn = xp + Nn * Dd;
        const bool more = (t + 1 < Ss);
        float nx[Dd];
#pragma unroll
        for (int d = 0; d < Dd; ++d) nx[d] = more ? __ldg(xn + d) : 0.0f;

        // u = x_t @ W_in + b_in ; blade0 += 1
        float u = bi;
#pragma unroll
        for (int d = 0; d < Dd; ++d) u = fmaf(w[d], cx[d], u);
        if (lane == 0) u += 1.0f;

        // delta_r = normalize(u)
        float r  = warp_rnorm(u);
        float dl = u * r;

        // geometric product: pn[lane] = sum_i sgn(i, i^lane) * dl[i] * ps[i^lane]
        float pn = 0.0f;
#pragma unroll
        for (int i = 0; i < 32; ++i) {
            float di = __shfl_sync(FULLMASK, dl, i);        // broadcast a[i]
            float pj = __shfl_xor_sync(FULLMASK, ps, i);    // ps[lane^i]
            pn = fmaf(di, __uint_as_float(__float_as_uint(pj) ^ smask[i]), pn);
        }

        // psi = normalize(pn)
        r  = warp_rnorm(pn);
        ps = pn * r;

        *pp = ps;        // coalesced 128B store per warp
        pp += HW;
        xp = xn;
#pragma unroll
        for (int d = 0; d < Dd; ++d) cx[d] = nx[d];
    }
}

// ---------------------------------------------------------------------------
// Phase 2: y[b,t,n,:] = x[b,t,n,:] + psi[b,n,t,:] @ W_out + b_out
// One warp per (chain,t) row; 512-length dot products vs 6 output dims.
// W_out staged in shared, transposed [d][c] for conflict-free LDS.
// ---------------------------------------------------------------------------
__global__ void __launch_bounds__(256) proj_kernel(
    const float* __restrict__ x,      // [B,S,N,D]
    const float* __restrict__ W_out,  // [H*32, D]
    const float* __restrict__ b_out,  // [D]
    float* __restrict__ y)            // [B,S,N,D]
{
    __shared__ float sW[Dd][HW];
    __shared__ float sB[Dd];
    for (int i = threadIdx.x; i < HW * Dd; i += blockDim.x) {
        int cc = i / Dd, d = i % Dd;
        sW[d][cc] = W_out[i];
    }
    if (threadIdx.x < Dd) sB[threadIdx.x] = b_out[threadIdx.x];
    __syncthreads();

    const int warpGlobal = (blockIdx.x * blockDim.x + threadIdx.x) >> 5;  // 0..2047
    const int lane = threadIdx.x & 31;

    for (int rr = 0; rr < 32; ++rr) {
        const int row = warpGlobal + 2048 * rr;            // 0..65535 = chain*256 + t
        const float* pr = g_psi + (size_t)row * HW;

        float a0 = 0.f, a1 = 0.f, a2 = 0.f, a3 = 0.f, a4 = 0.f, a5 = 0.f;
#pragma unroll
        for (int k = 0; k < 16; ++k) {
            const int cc = lane + 32 * k;                  // conflict-free banks
            const float p = __ldg(pr + cc);                // coalesced
            a0 = fmaf(p, sW[0][cc], a0);
            a1 = fmaf(p, sW[1][cc], a1);
            a2 = fmaf(p, sW[2][cc], a2);
            a3 = fmaf(p, sW[3][cc], a3);
            a4 = fmaf(p, sW[4][cc], a4);
            a5 = fmaf(p, sW[5][cc], a5);
        }
#pragma unroll
        for (int o = 16; o; o >>= 1) {
            a0 += __shfl_xor_sync(FULLMASK, a0, o);
            a1 += __shfl_xor_sync(FULLMASK, a1, o);
            a2 += __shfl_xor_sync(FULLMASK, a2, o);
            a3 += __shfl_xor_sync(FULLMASK, a3, o);
            a4 += __shfl_xor_sync(FULLMASK, a4, o);
            a5 += __shfl_xor_sync(FULLMASK, a5, o);
        }

        const int c = row >> 8;
        const int t = row & (Ss - 1);
        const int b = c >> 4;
        const int n = c & (Nn - 1);
        const size_t off = (((size_t)b * Ss + t) * Nn + n) * Dd;
        if (lane < Dd) {
            float av = (lane == 0) ? a0 : (lane == 1) ? a1 : (lane == 2) ? a2
                     : (lane == 3) ? a3 : (lane == 4) ? a4 : a5;
            y[off + lane] = x[off + lane] + av + sB[lane];
        }
    }
}

extern "C" void kernel_launch(void* const* d_in, const int* in_sizes, int n_in,
                              void* d_out, int out_size) {
    const float* x     = (const float*)d_in[0];
    const float* W_in  = (const float*)d_in[1];
    const float* b_in  = (const float*)d_in[2];
    const float* W_out = (const float*)d_in[3];
    const float* b_out = (const float*)d_in[4];
    float* y = (float*)d_out;

    // Phase 1: 4096 warps (256 chains x 16 heads), one warp per recurrence
    rotor_rnn_kernel<<<1024, 128>>>(x, W_in, b_in);
    // Phase 2: 2048 warps x 32 rows each = 65536 output rows
    proj_kernel<<<256, 256>>>(x, W_out, b_out, y);
}

// round 3
// speedup vs baseline: 1.5905x; 1.5849x over previous
#include <cuda_runtime.h>

#define FULLMASK 0xffffffffu

// Problem dims (fixed by the dataset)
#define Bb 16
#define Ss 256
#define Nn 16
#define Dd 6
#define Hh 16
#define CHAINS (Bb * Nn)   // 256
#define HW (Hh * 32)       // 512

// Scratch for all rotor states: [chain][t][h*32+blade] = 128 MB
__device__ float g_psi[(size_t)CHAINS * Ss * HW];

// rsqrt of head-norm: sum v^2 over 4 local regs + 8-lane group (masks 1,2,4)
__device__ __forceinline__ float qnorm8(const float v0, const float v1,
                                        const float v2, const float v3) {
    float s = v0 * v0 + v1 * v1;
    s = fmaf(v2, v2, s);
    s = fmaf(v3, v3, s);
    s += __shfl_xor_sync(FULLMASK, s, 1);
    s += __shfl_xor_sync(FULLMASK, s, 2);
    s += __shfl_xor_sync(FULLMASK, s, 4);
    s += 1e-8f;
    float r = rsqrtf(s);
    r = r * (1.5f - 0.5f * s * r * r);   // one NR step for 256-step stability
    return r;
}

// ---------------------------------------------------------------------------
// Phase 1: rotor recurrence. 8 lanes per head (4 blades/lane), 4 heads/warp
// (all same chain). 1024 warps total. Writes psi_t for every step to g_psi.
//
// GP: pn[k] = sum_j sgn(k^j, j) dl[k^j] ps[j], blade = g*4+r (g = lane&7).
// Sign B(a,j) = sum_{i>t} a_i j_t is GF(2)-bilinear:
//   B(a,j) = sigma(m, g^m)  [runtime, uniform over s,jr; applied to dl bcast]
//          ^ jr0*(kr1^jr1^P) ^ jr1*P   [compile-time, folded into FMA sign]
// where m = group-xor mask, P = parity(m), s = kr^jr.
// ---------------------------------------------------------------------------
__global__ void __launch_bounds__(128) rotor_rnn_kernel(
    const float* __restrict__ x,      // [B,S,N,D]
    const float* __restrict__ W_in,   // [D, H*32]
    const float* __restrict__ b_in)   // [H*32]
{
    const int gw   = (blockIdx.x * blockDim.x + threadIdx.x) >> 5;  // 0..1023
    const int lane = threadIdx.x & 31;
    const int c  = gw >> 2;           // chain 0..255
    const int hq = gw & 3;            // head quad within chain
    const int w  = lane >> 3;         // head within quad
    const int g  = lane & 7;          // blade group (blades g*4 .. g*4+3)
    const int h  = hq * 4 + w;
    const int b  = c >> 4;
    const int n  = c & (Nn - 1);
    const int col0 = h * 32 + g * 4;

    // W_in columns + bias for this lane's 4 blades
    float wi[4][Dd];
    float bi[4];
#pragma unroll
    for (int r = 0; r < 4; ++r) {
#pragma unroll
        for (int d = 0; d < Dd; ++d) wi[r][d] = __ldg(W_in + d * HW + col0 + r);
        bi[r] = __ldg(b_in + col0 + r);
    }

    // Per-(lane, mask) sigma sign: sigma = G0*(m1^m2) ^ G1*m2, G = g^m
    unsigned sm8[8];
#pragma unroll
    for (int m = 0; m < 8; ++m) {
        unsigned G  = (unsigned)(g ^ m);
        unsigned m1 = (m >> 1) & 1u, m2 = (m >> 2) & 1u;
        unsigned sgn = ((G & 1u) & (m1 ^ m2)) ^ (((G >> 1) & 1u) & m2);
        sm8[m] = sgn << 31;
    }

    // psi0 = identity rotor (blade 0 lives at g==0, r==0)
    float ps0 = (g == 0) ? 1.0f : 0.0f, ps1 = 0.f, ps2 = 0.f, ps3 = 0.f;

    const float* xp = x + ((size_t)(b * Ss) * Nn + n) * Dd;
    float4* pp = (float4*)(g_psi + ((size_t)c * Ss) * HW + col0);

    float cx[Dd];
#pragma unroll
    for (int d = 0; d < Dd; ++d) cx[d] = __ldg(xp + d);

    for (int t = 0; t < Ss; ++t) {
        // prefetch next x (warp-uniform broadcast)
        const float* xn = xp + Nn * Dd;
        const bool more = (t + 1 < Ss);
        float nx[Dd];
#pragma unroll
        for (int d = 0; d < Dd; ++d) nx[d] = more ? __ldg(xn + d) : 0.0f;

        // u = x_t @ W_in + b_in ; +1 on blade 0
        float u[4];
#pragma unroll
        for (int r = 0; r < 4; ++r) {
            float a = bi[r];
#pragma unroll
            for (int d = 0; d < Dd; ++d) a = fmaf(wi[r][d], cx[d], a);
            u[r] = a;
        }
        if (g == 0) u[0] += 1.0f;

        // delta_r = normalize(u)
        float rn = qnorm8(u[0], u[1], u[2], u[3]);
        float dl0 = u[0] * rn, dl1 = u[1] * rn, dl2 = u[2] * rn, dl3 = u[3] * rn;

        // geometric product (two accumulator banks for ILP)
        float pA0 = 0.f, pA1 = 0.f, pA2 = 0.f, pA3 = 0.f;
        float pB0 = 0.f, pB1 = 0.f, pB2 = 0.f, pB3 = 0.f;
#pragma unroll
        for (int m = 0; m < 8; ++m) {
            // ps[(g^m)*4 + jr]
            float pm0 = __shfl_xor_sync(FULLMASK, ps0, m);
            float pm1 = __shfl_xor_sync(FULLMASK, ps1, m);
            float pm2 = __shfl_xor_sync(FULLMASK, ps2, m);
            float pm3 = __shfl_xor_sync(FULLMASK, ps3, m);
            // dl[m*4 + s], signed with sigma(m)
            unsigned sg = sm8[m];
            float a0 = __uint_as_float(__float_as_uint(__shfl_sync(FULLMASK, dl0, m, 8)) ^ sg);
            float a1 = __uint_as_float(__float_as_uint(__shfl_sync(FULLMASK, dl1, m, 8)) ^ sg);
            float a2 = __uint_as_float(__float_as_uint(__shfl_sync(FULLMASK, dl2, m, 8)) ^ sg);
            float a3 = __uint_as_float(__float_as_uint(__shfl_sync(FULLMASK, dl3, m, 8)) ^ sg);

            const unsigned P = ((m) ^ (m >> 1) ^ (m >> 2)) & 1u;
            float& q0 = (m & 1) ? pB0 : pA0;
            float& q1 = (m & 1) ? pB1 : pA1;
            float& q2 = (m & 1) ? pB2 : pA2;
            float& q3 = (m & 1) ? pB3 : pA3;

            // residual sign (compile-time): neg = jr0*(kr1^jr1^P) ^ jr1*P
            // jr = 0: s = kr, sign +
            q0 = fmaf(a0, pm0, q0);
            q1 = fmaf(a1, pm0, q1);
            q2 = fmaf(a2, pm0, q2);
            q3 = fmaf(a3, pm0, q3);
            // jr = 1 (jr0=1, jr1=0): neg = kr1 ^ P ; s = kr^1
            if (P == 0) {
                q0 = fmaf( a1, pm1, q0);
                q1 = fmaf( a0, pm1, q1);
                q2 = fmaf(-a3, pm1, q2);
                q3 = fmaf(-a2, pm1, q3);
            } else {
                q0 = fmaf(-a1, pm1, q0);
                q1 = fmaf(-a0, pm1, q1);
                q2 = fmaf( a3, pm1, q2);
                q3 = fmaf( a2, pm1, q3);
            }
            // jr = 2 (jr0=0, jr1=1): neg = P ; s = kr^2
            if (P == 0) {
                q0 = fmaf( a2, pm2, q0);
                q1 = fmaf( a3, pm2, q1);
                q2 = fmaf( a0, pm2, q2);
                q3 = fmaf( a1, pm2, q3);
            } else {
                q0 = fmaf(-a2, pm2, q0);
                q1 = fmaf(-a3, pm2, q1);
                q2 = fmaf(-a0, pm2, q2);
                q3 = fmaf(-a1, pm2, q3);
            }
            // jr = 3 (jr0=1, jr1=1): neg = (kr1^1^P) ^ P = kr1^1 ; s = kr^3
            // kr=0,1 -> neg ; kr=2,3 -> pos  (independent of P)
            q0 = fmaf(-a3, pm3, q0);
            q1 = fmaf(-a2, pm3, q1);
            q2 = fmaf( a1, pm3, q2);
            q3 = fmaf( a0, pm3, q3);
        }
        float pn0 = pA0 + pB0, pn1 = pA1 + pB1, pn2 = pA2 + pB2, pn3 = pA3 + pB3;

        // psi = normalize(pn)
        rn  = qnorm8(pn0, pn1, pn2, pn3);
        ps0 = pn0 * rn; ps1 = pn1 * rn; ps2 = pn2 * rn; ps3 = pn3 * rn;

        *pp = make_float4(ps0, ps1, ps2, ps3);   // one STG.128/lane, coalesced
        pp += HW / 4;
        xp = xn;
#pragma unroll
        for (int d = 0; d < Dd; ++d) cx[d] = nx[d];
    }
}

// ---------------------------------------------------------------------------
// Phase 2: y[b,t,n,:] = x[b,t,n,:] + psi_row @ W_out + b_out
// W_out held in registers (96/lane); psi read as float4. 4096 warps x 16 rows.
// ---------------------------------------------------------------------------
__global__ void __launch_bounds__(256) proj_kernel(
    const float* __restrict__ x,      // [B,S,N,D]
    const float* __restrict__ W_out,  // [H*32, D]
    const float* __restrict__ b_out,  // [D]
    float* __restrict__ y)            // [B,S,N,D]
{
    const int warpId = (blockIdx.x * blockDim.x + threadIdx.x) >> 5;  // 0..4095
    const int lane   = threadIdx.x & 31;

    // This lane's 16 W_out columns: cc = k*128 + lane*4 + q
    float wv[16][Dd];
#pragma unroll
    for (int k = 0; k < 4; ++k)
#pragma unroll
        for (int q = 0; q < 4; ++q) {
            const int cc = k * 128 + lane * 4 + q;
#pragma unroll
            for (int d = 0; d < Dd; ++d)
                wv[k * 4 + q][d] = __ldg(W_out + cc * Dd + d);
        }
    const float bo = (lane < Dd) ? __ldg(b_out + lane) : 0.0f;

    for (int rr = 0; rr < 16; ++rr) {
        const int row = warpId + 4096 * rr;          // chain*256 + t
        const float4* pr = (const float4*)(g_psi + (size_t)row * HW) + lane;

        float a0 = 0.f, a1 = 0.f, a2 = 0.f, a3 = 0.f, a4 = 0.f, a5 = 0.f;
#pragma unroll
        for (int k = 0; k < 4; ++k) {
            const float4 p = __ldg(pr + k * 32);     // LDG.128, coalesced
            const float* wp0 = wv[k * 4 + 0];
            const float* wp1 = wv[k * 4 + 1];
            const float* wp2 = wv[k * 4 + 2];
            const float* wp3 = wv[k * 4 + 3];
            a0 = fmaf(p.x, wp0[0], a0); a1 = fmaf(p.x, wp0[1], a1);
            a2 = fmaf(p.x, wp0[2], a2); a3 = fmaf(p.x, wp0[3], a3);
            a4 = fmaf(p.x, wp0[4], a4); a5 = fmaf(p.x, wp0[5], a5);
            a0 = fmaf(p.y, wp1[0], a0); a1 = fmaf(p.y, wp1[1], a1);
            a2 = fmaf(p.y, wp1[2], a2); a3 = fmaf(p.y, wp1[3], a3);
            a4 = fmaf(p.y, wp1[4], a4); a5 = fmaf(p.y, wp1[5], a5);
            a0 = fmaf(p.z, wp2[0], a0); a1 = fmaf(p.z, wp2[1], a1);
            a2 = fmaf(p.z, wp2[2], a2); a3 = fmaf(p.z, wp2[3], a3);
            a4 = fmaf(p.z, wp2[4], a4); a5 = fmaf(p.z, wp2[5], a5);
            a0 = fmaf(p.w, wp3[0], a0); a1 = fmaf(p.w, wp3[1], a1);
            a2 = fmaf(p.w, wp3[2], a2); a3 = fmaf(p.w, wp3[3], a3);
            a4 = fmaf(p.w, wp3[4], a4); a5 = fmaf(p.w, wp3[5], a5);
        }
#pragma unroll
        for (int o = 16; o; o >>= 1) {
            a0 += __shfl_xor_sync(FULLMASK, a0, o);
            a1 += __shfl_xor_sync(FULLMASK, a1, o);
            a2 += __shfl_xor_sync(FULLMASK, a2, o);
            a3 += __shfl_xor_sync(FULLMASK, a3, o);
            a4 += __shfl_xor_sync(FULLMASK, a4, o);
            a5 += __shfl_xor_sync(FULLMASK, a5, o);
        }

        const int c = row >> 8;
        const int t = row & (Ss - 1);
        const int b = c >> 4;
        const int n = c & (Nn - 1);
        const size_t off = (((size_t)b * Ss + t) * Nn + n) * Dd;
        if (lane < Dd) {
            float av = (lane == 0) ? a0 : (lane == 1) ? a1 : (lane == 2) ? a2
                     : (lane == 3) ? a3 : (lane == 4) ? a4 : a5;
            y[off + lane] = x[off + lane] + av + bo;
        }
    }
}

extern "C" void kernel_launch(void* const* d_in, const int* in_sizes, int n_in,
                              void* d_out, int out_size) {
    const float* x     = (const float*)d_in[0];
    const float* W_in  = (const float*)d_in[1];
    const float* b_in  = (const float*)d_in[2];
    const float* W_out = (const float*)d_in[3];
    const float* b_out = (const float*)d_in[4];
    float* y = (float*)d_out;

    // Phase 1: 1024 warps = 256 chains x 4 head-quads (4 heads per warp)
    rotor_rnn_kernel<<<256, 128>>>(x, W_in, b_in);
    // Phase 2: 4096 warps x 16 rows = 65536 output rows
    proj_kernel<<<512, 256>>>(x, W_out, b_out, y);
}